// round 15
// baseline (speedup 1.0000x reference)
#include <cuda_runtime.h>
#include <cuda_fp16.h>
#include <mma.h>
#include <cstdint>

using namespace nvcuda;

#define HH 192
#define WW 192
#define HWSZ (192*192)
#define CC 64
#define KTAPS 49
#define PADK 3

#define FMA2(d,a,b,c) asm("fma.rn.f32x2 %0, %1, %2, %3;" : "=l"(d) : "l"(a), "l"(b), "l"(c))

typedef unsigned long long ull;

__device__ __forceinline__ ull packpair(float v) {
    unsigned int u = __float_as_uint(v);
    return ((ull)u << 32) | u;
}
__device__ __forceinline__ ull pack2(float lo, float hi) {
    return ((ull)__float_as_uint(hi) << 32) | __float_as_uint(lo);
}

// ---------------- scratch (no allocs allowed) ----------------
__device__ float  g_rev [CC*HWSZ];
__device__ float  g_fft [CC*HWSZ];
__device__ __half g_encTh[HWSZ*CC];       // NHWC fp16
__device__ float  g_e2pm[CC*64*576];      // [c][q=64][patch=576]
__device__ __half g_wfh[KTAPS*64*64];     // [k][o][c] fp16 deform weight
__device__ __half g_wc3h[9*64*64];        // [k][o][c] fp16 conv3 hi
__device__ __half g_wc3l[9*64*64];        // [k][o][c] fp16 conv3 lo
__device__ __half g_wpf [128*128];        // [o128][j128] fp16 proj weight
__device__ ull    g_wpit2[64*64];         // [j][c] pairs
__device__ float  g_gg  [64*64];          // [c][a*8+d]

// ---------------- precompute: FFT filter -> circular conv kernel ----------------
__global__ void k_prep_g(const float* __restrict__ fw) {
    int c = blockIdx.x;
    int t = threadIdx.x;
    int a = t >> 3, d = t & 7;
    const float ct[8] = {1.f, 0.70710678118654752f, 0.f, -0.70710678118654752f,
                        -1.f, -0.70710678118654752f, 0.f, 0.70710678118654752f};
    const float st[8] = {0.f, 0.70710678118654752f, 1.f, 0.70710678118654752f,
                         0.f, -0.70710678118654752f, -1.f, -0.70710678118654752f};
    const float* w = fw + c * 40;
    float re = 0.f;
    for (int u = 0; u < 8; u++) {
        float rp = w[u*5+0] + ((d & 1) ? -w[u*5+4] : w[u*5+4]);
        float ip = 0.f;
        #pragma unroll
        for (int v = 1; v <= 3; v++) {
            int vd = (v * d) & 7;
            rp += 2.f * w[u*5+v] * ct[vd];
            ip += 2.f * w[u*5+v] * st[vd];
        }
        int ua = (u * a) & 7;
        re += ct[ua] * rp - st[ua] * ip;
    }
    g_gg[c*64 + t] = re * (1.f/64.f);
}

// ---------------- precompute: fused deform weight -> fp16 [k][o][c] ----------------
__global__ void k_prep_wf(const float* __restrict__ wc1, const float* __restrict__ wd) {
    int idx = blockIdx.x * blockDim.x + threadIdx.x;   // k*4096 + c*64 + o
    if (idx >= KTAPS*64*64) return;
    int o = idx & 63, c = (idx >> 6) & 63, k = idx >> 12;
    float s = 0.f;
    for (int m = 0; m < 64; m++)
        s += wc1[o*64 + m] * wd[(m*64 + c)*49 + k];
    g_wfh[k*4096 + o*64 + c] = __float2half(s);
}

// ---------------- precompute: conv3 fp16 hi/lo + proj fp16 + wpit pairs ----------------
__global__ void k_prep_tr(const float* __restrict__ wc2, const float* __restrict__ wpo,
                          const float* __restrict__ wpi) {
    int idx = blockIdx.x * blockDim.x + threadIdx.x;
    if (idx < 9*4096) {                          // [k][o][c] <- wc2[o][c][k]
        int o = idx & 63, c = (idx >> 6) & 63, k = idx >> 12;
        float s = wc2[(o*64 + c)*9 + k];
        __half hi = __float2half(s);
        float hv = __half2float(hi);
        g_wc3h[k*4096 + o*64 + c] = hi;
        g_wc3l[k*4096 + o*64 + c] = __float2half(s - hv);
    }
    if (idx < 128*128) {                         // [o][j] fp16 copy
        g_wpf[idx] = __float2half(wpo[idx]);
    }
    if (idx < 4096) {                            // [j][c] pairs
        int j = idx >> 6, c = idx & 63;
        g_wpit2[idx] = packpair(wpi[c*64 + j]);
    }
}

// ---------------- NCHW -> NHWC fp16 transpose of enc ----------------
__global__ void __launch_bounds__(256) k_transpose(const float* __restrict__ enc) {
    __shared__ float S[64][65];
    int tid = threadIdx.x;
    int p0 = blockIdx.x * 64;
    #pragma unroll
    for (int i = 0; i < 16; i++) {
        int e = i*256 + tid;
        S[e >> 6][e & 63] = enc[(e >> 6)*HWSZ + p0 + (e & 63)];
    }
    __syncthreads();
    #pragma unroll
    for (int i = 0; i < 8; i++) {
        int e2 = i*512 + tid*2;
        int lp = e2 >> 6, c = e2 & 63;
        __half2 hp = __floats2half2_rn(S[c][lp], S[c+1][lp]);
        *(__half2*)&g_encTh[p0*64 + e2] = hp;
    }
}

// ---------------- mega: deform (blocks 0..287, double-buffered pipeline)
//                        + 1x1 conv branch (blocks 288..431) ----------------
// deform smem: VF0 0..18432 | VF1 ..36864 | WH0 ..46080 | WH1 ..55296
//              SIDX0 ..57344 | SIDX1 ..59392 | SWT0 ..61440 | SWT1 ..63488
// readout Dsh (34816B) overlays VF0. conv branch uses first 32KB as Wt.
#define MG_VF0   0
#define MG_VF1   18432
#define MG_WH0   36864
#define MG_WH1   46080
#define MG_SIDX0 55296
#define MG_SIDX1 57344
#define MG_SWT0  59392
#define MG_SWT1  61440
#define MG_SMEM  63488

__global__ void __launch_bounds__(256, 2) k_mega(const float* __restrict__ off,
                                                 const float* __restrict__ msk,
                                                 const float* __restrict__ enc) {
    extern __shared__ char dsm[];
    int tid = threadIdx.x;
    int b = blockIdx.x;

    if (b < 288) {
        // ================= deform branch =================
        __half* VfB[2] = { (__half*)(dsm + MG_VF0), (__half*)(dsm + MG_VF1) };
        __half* WhB[2] = { (__half*)(dsm + MG_WH0), (__half*)(dsm + MG_WH1) };
        int*   sIdxB[2] = { (int*)(dsm + MG_SIDX0), (int*)(dsm + MG_SIDX1) };
        float* sWtB[2]  = { (float*)(dsm + MG_SWT0), (float*)(dsm + MG_SWT1) };
        const __half* encT = g_encTh;

        int wid = tid >> 5;
        int mg = wid & 3, ng = wid >> 2;
        int ph = (b / 12) * 8, pw = (b % 12) * 16;
        int ly = (tid & 127) >> 4, lx = tid & 15;
        int h = ph + ly, w = pw + lx;
        int sp = h * WW + w;

        wmma::fragment<wmma::accumulator, 16, 16, 16, float> dfr[2][2];
        #pragma unroll
        for (int mf = 0; mf < 2; mf++)
            #pragma unroll
            for (int nf = 0; nf < 2; nf++) wmma::fill_fragment(dfr[mf][nf], 0.f);

        // ---- pipeline helpers as macros over k/buf ----
        #define STAGE_W(kk, bb) do { \
            __half* Wh = WhB[bb]; \
            _Pragma("unroll") \
            for (int i = 0; i < 2; i++) { \
                int f = i*256 + tid; \
                int row = f >> 3, ch = f & 7; \
                *(float4*)((char*)Wh + row*144 + ch*16) = \
                    *(const float4*)(g_wfh + (kk)*4096 + row*64 + ch*8); \
            } \
        } while (0)

        #define STAGE_P(kk, bb) do { \
            if (tid < 128) { \
                int* sIdx = sIdxB[bb]; float* sWt = sWtB[bb]; \
                float dy = off[(2*(kk))*HWSZ + sp]; \
                float dx = off[(2*(kk)+1)*HWSZ + sp]; \
                float m  = msk[(kk)*HWSZ + sp]; \
                float yy = (float)(h - PADK + (kk)/7) + dy; \
                float xx = (float)(w - PADK + (kk)%7) + dx; \
                float y0f = floorf(yy), x0f = floorf(xx); \
                float wy = yy - y0f, wx = xx - x0f; \
                int y0 = (int)y0f, x0 = (int)x0f; \
                int y1 = y0 + 1,   x1 = x0 + 1; \
                bool vy0 = (y0 >= 0) && (y0 < HH), vy1 = (y1 >= 0) && (y1 < HH); \
                bool vx0 = (x0 >= 0) && (x0 < WW), vx1 = (x1 >= 0) && (x1 < WW); \
                int y0c = min(max(y0, 0), HH-1), y1c = min(max(y1, 0), HH-1); \
                int x0c = min(max(x0, 0), WW-1), x1c = min(max(x1, 0), WW-1); \
                sIdx[0*128 + tid] = (y0c*WW + x0c) * 64; \
                sIdx[1*128 + tid] = (y0c*WW + x1c) * 64; \
                sIdx[2*128 + tid] = (y1c*WW + x0c) * 64; \
                sIdx[3*128 + tid] = (y1c*WW + x1c) * 64; \
                sWt[0*128 + tid] = (vy0 && vx0) ? (1.f-wy)*(1.f-wx)*m : 0.f; \
                sWt[1*128 + tid] = (vy0 && vx1) ? (1.f-wy)*wx*m       : 0.f; \
                sWt[2*128 + tid] = (vy1 && vx0) ? wy*(1.f-wx)*m       : 0.f; \
                sWt[3*128 + tid] = (vy1 && vx1) ? wy*wx*m             : 0.f; \
            } \
        } while (0)

        #define GATHER(bb) do { \
            __half* Vf = VfB[bb]; int* sIdx = sIdxB[bb]; float* sWt = sWtB[bb]; \
            int c8 = tid & 7; \
            _Pragma("unroll") \
            for (int it = 0; it < 4; it++) { \
                int p = (tid >> 3) + it * 32; \
                uint4 q0 = *(const uint4*)(encT + sIdx[0*128 + p] + (c8 << 3)); \
                uint4 q1 = *(const uint4*)(encT + sIdx[1*128 + p] + (c8 << 3)); \
                uint4 q2 = *(const uint4*)(encT + sIdx[2*128 + p] + (c8 << 3)); \
                uint4 q3 = *(const uint4*)(encT + sIdx[3*128 + p] + (c8 << 3)); \
                float w0 = sWt[0*128 + p], w1 = sWt[1*128 + p]; \
                float w2 = sWt[2*128 + p], w3 = sWt[3*128 + p]; \
                const uint32_t* u0 = (const uint32_t*)&q0; \
                const uint32_t* u1 = (const uint32_t*)&q1; \
                const uint32_t* u2 = (const uint32_t*)&q2; \
                const uint32_t* u3 = (const uint32_t*)&q3; \
                uint32_t r[4]; \
                _Pragma("unroll") \
                for (int j = 0; j < 4; j++) { \
                    float2 a0 = __half22float2(*(const __half2*)&u0[j]); \
                    float2 a1 = __half22float2(*(const __half2*)&u1[j]); \
                    float2 a2 = __half22float2(*(const __half2*)&u2[j]); \
                    float2 a3 = __half22float2(*(const __half2*)&u3[j]); \
                    float vx = w0*a0.x + w1*a1.x + w2*a2.x + w3*a3.x; \
                    float vy = w0*a0.y + w1*a1.y + w2*a2.y + w3*a3.y; \
                    asm("cvt.rn.f16x2.f32 %0, %1, %2;" : "=r"(r[j]) : "f"(vy), "f"(vx)); \
                } \
                *(uint4*)((char*)Vf + p*144 + (c8 << 4)) = *(uint4*)r; \
            } \
        } while (0)

        // ---- prologue ----
        STAGE_W(0, 0);
        STAGE_P(0, 0);
        __syncthreads();
        GATHER(0);
        __syncthreads();

        // ---- pipelined taps: 2 syncs per tap ----
        for (int k = 0; k < KTAPS; k++) {
            int cur = k & 1, nxt = (k + 1) & 1;
            if (k < KTAPS - 1) {
                STAGE_W(k + 1, nxt);
                STAGE_P(k + 1, nxt);
            }
            {
                __half* Vf = VfB[cur];
                __half* Wh = WhB[cur];
                #pragma unroll
                for (int kc = 0; kc < 4; kc++) {
                    wmma::fragment<wmma::matrix_a, 16, 16, 16, __half, wmma::row_major> af[2];
                    #pragma unroll
                    for (int mf = 0; mf < 2; mf++)
                        wmma::load_matrix_sync(af[mf], Vf + (mg*32 + mf*16)*72 + kc*16, 72);
                    #pragma unroll
                    for (int nf = 0; nf < 2; nf++) {
                        wmma::fragment<wmma::matrix_b, 16, 16, 16, __half, wmma::col_major> bh;
                        wmma::load_matrix_sync(bh, Wh + (ng*32 + nf*16)*72 + kc*16, 72);
                        #pragma unroll
                        for (int mf = 0; mf < 2; mf++)
                            wmma::mma_sync(dfr[mf][nf], af[mf], bh, dfr[mf][nf]);
                    }
                }
            }
            __syncthreads();
            if (k < KTAPS - 1) GATHER(nxt);
            __syncthreads();
        }

        // ---- readout ----
        float* Dsh = (float*)dsm;
        #pragma unroll
        for (int mf = 0; mf < 2; mf++)
            #pragma unroll
            for (int nf = 0; nf < 2; nf++)
                wmma::store_matrix_sync(Dsh + (mg*32 + mf*16)*68 + ng*32 + nf*16,
                                        dfr[mf][nf], 68, wmma::mem_row_major);
        __syncthreads();
        {
            int p = tid & 127;
            int hf = tid >> 7;
            int base = (ph + (p >> 4))*WW + pw + (p & 15);
            #pragma unroll
            for (int i = 0; i < 32; i++) {
                int o = hf*32 + i;
                g_rev[o*HWSZ + base] = Dsh[p*68 + o];
            }
        }
        #undef STAGE_W
        #undef STAGE_P
        #undef GATHER
    } else {
        // ================= 1x1 conv branch (enc -> e2pm) =================
        ull* Wt = (ull*)dsm;   // 32768 B
        int cb = b - 288;      // 0..143
        {
            const ulonglong2* src = (const ulonglong2*)g_wpit2;
            ulonglong2* dst = (ulonglong2*)Wt;
            #pragma unroll
            for (int i = 0; i < 8; i++) dst[tid + i*256] = src[tid + i*256];
        }
        __syncthreads();

        int pairIdx = tid >> 1, half = tid & 1;
        int base = cb * 256;
        int p = base + (pairIdx & 7) + (pairIdx >> 3) * 16;
        int p2 = p + 8;

        ull acc[32];
        #pragma unroll
        for (int i = 0; i < 32; i++) acc[i] = 0ull;

        for (int j = 0; j < 64; j++) {
            ull v = pack2(enc[j*HWSZ + p], enc[j*HWSZ + p2]);
            const ulonglong2* wrow = (const ulonglong2*)(Wt + j*64 + half*32);
            #pragma unroll
            for (int cc = 0; cc < 16; cc++) {
                ulonglong2 wv = wrow[cc];
                FMA2(acc[2*cc],   wv.x, v, acc[2*cc]);
                FMA2(acc[2*cc+1], wv.y, v, acc[2*cc+1]);
            }
        }

        int h = p / 192, w = p % 192;
        int q = (h & 7)*8 + (w & 7);
        int pat = (h >> 3)*24 + (w >> 3);
        #pragma unroll
        for (int i = 0; i < 32; i++) {
            int c = half*32 + i;
            *(ull*)&g_e2pm[c*(64*576) + q*576 + pat] = acc[i];
        }
    }
}

// ---------------- per-patch circular conv as dense GEMM per channel ----------------
#define FFT_SMEM (50176 + 32768)

__global__ void __launch_bounds__(256, 2) k_fftgemm() {
    extern __shared__ char dsm[];
    float* Es = (float*)dsm;
    ull*   Wp = (ull*)(dsm + 50176);

    int tid = threadIdx.x;
    int lane = tid & 31;
    int c = blockIdx.x, pg = blockIdx.y;

    #pragma unroll
    for (int i = 0; i < 12; i++) {
        int f = i*256 + tid;
        int q = f / 48, r = f % 48;
        *(float4*)&Es[q*196 + r*4] =
            *(const float4*)&g_e2pm[c*(64*576) + q*576 + pg*192 + r*4];
    }
    #pragma unroll
    for (int i = 0; i < 16; i++) {
        int f = i*256 + tid;
        int q = f >> 6, p = f & 63;
        int idx = (((p >> 3) - (q >> 3)) & 7)*8 + (((p & 7) - (q & 7)) & 7);
        Wp[f] = packpair(g_gg[c*64 + idx]);
    }
    __syncthreads();

    int pbase = (tid >> 5) * 8;
    ull acc[8][3];
    #pragma unroll
    for (int o = 0; o < 8; o++)
        #pragma unroll
        for (int g = 0; g < 3; g++) acc[o][g] = 0ull;

    #pragma unroll 8
    for (int q = 0; q < 64; q++) {
        ull A0 = *(const ull*)&Es[q*196 + 0*64 + 2*lane];
        ull A1 = *(const ull*)&Es[q*196 + 1*64 + 2*lane];
        ull A2 = *(const ull*)&Es[q*196 + 2*64 + 2*lane];
        const ulonglong2* wp = (const ulonglong2*)(Wp + q*64 + pbase);
        ulonglong2 w01 = wp[0], w23 = wp[1], w45 = wp[2], w67 = wp[3];
        ull wv[8] = {w01.x, w01.y, w23.x, w23.y, w45.x, w45.y, w67.x, w67.y};
        #pragma unroll
        for (int o = 0; o < 8; o++) {
            FMA2(acc[o][0], wv[o], A0, acc[o][0]);
            FMA2(acc[o][1], wv[o], A1, acc[o][1]);
            FMA2(acc[o][2], wv[o], A2, acc[o][2]);
        }
    }

    float* dst = g_fft + c*HWSZ;
    #pragma unroll
    for (int o = 0; o < 8; o++) {
        int p = pbase + o;
        int py = p >> 3, px = p & 7;
        #pragma unroll
        for (int g = 0; g < 3; g++) {
            int pat = pg*192 + g*64 + 2*lane;
            float lo = __uint_as_float((unsigned int)(acc[o][g] & 0xffffffffull));
            float hi = __uint_as_float((unsigned int)(acc[o][g] >> 32));
            dst[((pat/24)*8 + py)*WW + (pat%24)*8 + px] = lo;
            pat++;
            dst[((pat/24)*8 + py)*WW + (pat%24)*8 + px] = hi;
        }
    }
}

// ---------------- fused tail: halo + conv3x3 (WMMA, W hi/lo) + proj + gate ----------------
#define T_HS   0
#define T_WC3  23040
#define T_VF   41472
#define T_E3   76288
#define T_SMEM 111104

__global__ void __launch_bounds__(256, 2) k_tail(const float* __restrict__ dec,
                                                 float* __restrict__ out) {
    extern __shared__ char dsm[];
    __half* HS  = (__half*)(dsm + T_HS);
    __half* Wa  = (__half*)(dsm + T_WC3);
    __half* Wb  = (__half*)(dsm + T_WC3 + 9216);
    __half* Vf  = (__half*)(dsm + T_VF);
    float*  Dsh = (float*)(dsm + T_VF);
    __half* E3f = (__half*)(dsm + T_E3);
    __half* Wp  = (__half*)(dsm + T_HS);         // overlay after conv3

    int tid = threadIdx.x;
    int wid = tid >> 5;
    int mg = wid & 3, ng = wid >> 2;
    int ph = blockIdx.y * 8, pw = blockIdx.x * 16;

    for (int i = tid; i < 64*180; i += 256) {
        int c = i / 180, t = i - c*180;
        int hy = ph - 1 + t / 18, wx = pw - 1 + (t % 18);
        bool ok = (hy >= 0) && (hy < HH) && (wx >= 0) && (wx < WW);
        int sp = hy*WW + wx;
        float v = ok ? (g_fft[c*HWSZ + sp] + g_rev[c*HWSZ + sp]) : 0.f;
        HS[i] = __float2half(v);
    }

    wmma::fragment<wmma::accumulator, 16, 16, 16, float> a3[2][2];
    #pragma unroll
    for (int mf = 0; mf < 2; mf++)
        #pragma unroll
        for (int nf = 0; nf < 2; nf++) wmma::fill_fragment(a3[mf][nf], 0.f);

    for (int k = 0; k < 9; k++) {
        int dy = k/3 - 1, dx = k%3 - 1;
        #pragma unroll
        for (int i = 0; i < 2; i++) {
            int f = i*256 + tid;
            int row = f >> 3, ch = f & 7;
            *(float4*)((char*)Wa + row*144 + ch*16) =
                *(const float4*)(g_wc3h + k*4096 + row*64 + ch*8);
            *(float4*)((char*)Wb + row*144 + ch*16) =
                *(const float4*)(g_wc3l + k*4096 + row*64 + ch*8);
        }
        __syncthreads();
        #pragma unroll
        for (int i = 0; i < 32; i++) {
            int e = i*256 + tid;
            int c = e >> 7, p = e & 127;
            Vf[p*72 + c] = HS[c*180 + ((p >> 4) + 1 + dy)*18 + (p & 15) + 1 + dx];
        }
        __syncthreads();

        #pragma unroll
        for (int kc = 0; kc < 4; kc++) {
            wmma::fragment<wmma::matrix_a, 16, 16, 16, __half, wmma::row_major> af[2];
            #pragma unroll
            for (int mf = 0; mf < 2; mf++)
                wmma::load_matrix_sync(af[mf], Vf + (mg*32 + mf*16)*72 + kc*16, 72);
            #pragma unroll
            for (int nf = 0; nf < 2; nf++) {
                wmma::fragment<wmma::matrix_b, 16, 16, 16, __half, wmma::col_major> bh, bl;
                wmma::load_matrix_sync(bh, Wa + (ng*32 + nf*16)*72 + kc*16, 72);
                wmma::load_matrix_sync(bl, Wb + (ng*32 + nf*16)*72 + kc*16, 72);
                #pragma unroll
                for (int mf = 0; mf < 2; mf++) {
                    wmma::mma_sync(a3[mf][nf], af[mf], bh, a3[mf][nf]);
                    wmma::mma_sync(a3[mf][nf], af[mf], bl, a3[mf][nf]);
                }
            }
        }
        __syncthreads();
    }

    #pragma unroll
    for (int mf = 0; mf < 2; mf++)
        #pragma unroll
        for (int nf = 0; nf < 2; nf++)
            wmma::store_matrix_sync(Dsh + (mg*32 + mf*16)*68 + ng*32 + nf*16,
                                    a3[mf][nf], 68, wmma::mem_row_major);
    __syncthreads();

    {
        int p = tid & 127, hf = tid >> 7;
        int sp = (ph + (p >> 4))*WW + pw + (p & 15);
        #pragma unroll
        for (int i = 0; i < 32; i++) {
            int c = hf*32 + i;
            E3f[p*136 + c]      = __float2half(Dsh[p*68 + c]);
            E3f[p*136 + 64 + c] = __float2half(dec[c*HWSZ + sp]);
        }
    }
    __syncthreads();
    #pragma unroll
    for (int i = 0; i < 8; i++) {
        int f = i*256 + tid;            // 0..2047 : row = f>>4 (128), ch = f&15
        int row = f >> 4, ch = f & 15;
        *(float4*)((char*)Wp + row*272 + ch*16) =
            *(const float4*)(g_wpf + row*128 + ch*8);
    }
    __syncthreads();

    wmma::fragment<wmma::accumulator, 16, 16, 16, float> a1[2][2], a2[2][2];
    #pragma unroll
    for (int mf = 0; mf < 2; mf++)
        #pragma unroll
        for (int nf = 0; nf < 2; nf++) {
            wmma::fill_fragment(a1[mf][nf], 0.f);
            wmma::fill_fragment(a2[mf][nf], 0.f);
        }

    #pragma unroll
    for (int kc = 0; kc < 8; kc++) {
        wmma::fragment<wmma::matrix_a, 16, 16, 16, __half, wmma::row_major> af[2];
        #pragma unroll
        for (int mf = 0; mf < 2; mf++)
            wmma::load_matrix_sync(af[mf], E3f + (mg*32 + mf*16)*136 + kc*16, 136);
        #pragma unroll
        for (int nf = 0; nf < 2; nf++) {
            wmma::fragment<wmma::matrix_b, 16, 16, 16, __half, wmma::col_major> b1, b2;
            wmma::load_matrix_sync(b1, Wp + (ng*32 + nf*16)*136 + kc*16, 136);
            wmma::load_matrix_sync(b2, Wp + (64 + ng*32 + nf*16)*136 + kc*16, 136);
            #pragma unroll
            for (int mf = 0; mf < 2; mf++) {
                wmma::mma_sync(a1[mf][nf], af[mf], b1, a1[mf][nf]);
                wmma::mma_sync(a2[mf][nf], af[mf], b2, a2[mf][nf]);
            }
        }
    }

    #pragma unroll
    for (int mf = 0; mf < 2; mf++)
        #pragma unroll
        for (int nf = 0; nf < 2; nf++)
            #pragma unroll
            for (int i = 0; i < a1[mf][nf].num_elements; i++)
                a1[mf][nf].x[i] *= a2[mf][nf].x[i];

    __syncthreads();
    #pragma unroll
    for (int mf = 0; mf < 2; mf++)
        #pragma unroll
        for (int nf = 0; nf < 2; nf++)
            wmma::store_matrix_sync(Dsh + (mg*32 + mf*16)*68 + ng*32 + nf*16,
                                    a1[mf][nf], 68, wmma::mem_row_major);
    __syncthreads();
    {
        int p = tid & 127, hf = tid >> 7;
        int base = (ph + (p >> 4))*WW + pw + (p & 15);
        #pragma unroll
        for (int i = 0; i < 32; i++) {
            int o = hf*32 + i;
            out[o*HWSZ + base] = Dsh[p*68 + o];
        }
    }
}

extern "C" void kernel_launch(void* const* d_in, const int* in_sizes, int n_in,
                              void* d_out, int out_size) {
    const float* enc  = (const float*)d_in[0];
    const float* dec  = (const float*)d_in[1];
    const float* ioff = (const float*)d_in[2];
    const float* iw   = (const float*)d_in[3];
    const float* wpi  = (const float*)d_in[4];
    const float* fftw = (const float*)d_in[5];
    const float* wpo  = (const float*)d_in[6];
    const float* wdef = (const float*)d_in[7];
    const float* wc1  = (const float*)d_in[8];
    const float* wc2  = (const float*)d_in[9];
    float* out = (float*)d_out;

    cudaFuncSetAttribute(k_mega,    cudaFuncAttributeMaxDynamicSharedMemorySize, MG_SMEM);
    cudaFuncSetAttribute(k_fftgemm, cudaFuncAttributeMaxDynamicSharedMemorySize, FFT_SMEM);
    cudaFuncSetAttribute(k_tail,    cudaFuncAttributeMaxDynamicSharedMemorySize, T_SMEM);

    dim3 gfft(64, 3);
    dim3 gtail(12, 24);

    k_transpose<<<576, 256>>>(enc);
    k_prep_wf  <<<(KTAPS*4096 + 255)/256, 256>>>(wc1, wdef);
    k_prep_g   <<<64, 64>>>(fftw);
    k_prep_tr  <<<144, 256>>>(wc2, wpo, wpi);
    k_mega     <<<432, 256, MG_SMEM>>>(ioff, iw, enc);
    k_fftgemm  <<<gfft, 256, FFT_SMEM>>>();
    k_tail     <<<gtail, 256, T_SMEM>>>(dec, out);
}

// round 16
// speedup vs baseline: 1.2190x; 1.2190x over previous
#include <cuda_runtime.h>
#include <cuda_fp16.h>
#include <mma.h>
#include <cstdint>

using namespace nvcuda;

#define HH 192
#define WW 192
#define HWSZ (192*192)
#define CC 64
#define KTAPS 49
#define PADK 3

#define FMA2(d,a,b,c) asm("fma.rn.f32x2 %0, %1, %2, %3;" : "=l"(d) : "l"(a), "l"(b), "l"(c))

typedef unsigned long long ull;

__device__ __forceinline__ ull packpair(float v) {
    unsigned int u = __float_as_uint(v);
    return ((ull)u << 32) | u;
}
__device__ __forceinline__ ull pack2(float lo, float hi) {
    return ((ull)__float_as_uint(hi) << 32) | __float_as_uint(lo);
}

// ---------------- scratch (no allocs allowed) ----------------
__device__ float  g_rev [CC*HWSZ];
__device__ float  g_fft [CC*HWSZ];
__device__ __half g_encTh[HWSZ*CC];       // NHWC fp16
__device__ float  g_e2pm[CC*64*576];      // [c][q=64][patch=576]
__device__ __half g_wfh[KTAPS*64*64];     // [k][o][c] fp16 deform weight
__device__ __half g_wc3h[9*64*64];        // [k][o][c] fp16 conv3 hi
__device__ __half g_wc3l[9*64*64];        // [k][o][c] fp16 conv3 lo
__device__ __half g_wpf [128*128];        // [o128][j128] fp16 proj weight
__device__ ull    g_wpit2[64*64];         // [j][c] pairs
__device__ float  g_gg  [64*64];          // [c][a*8+d]

// ---------------- precompute: FFT filter -> circular conv kernel ----------------
__global__ void k_prep_g(const float* __restrict__ fw) {
    int c = blockIdx.x;
    int t = threadIdx.x;
    int a = t >> 3, d = t & 7;
    const float ct[8] = {1.f, 0.70710678118654752f, 0.f, -0.70710678118654752f,
                        -1.f, -0.70710678118654752f, 0.f, 0.70710678118654752f};
    const float st[8] = {0.f, 0.70710678118654752f, 1.f, 0.70710678118654752f,
                         0.f, -0.70710678118654752f, -1.f, -0.70710678118654752f};
    const float* w = fw + c * 40;
    float re = 0.f;
    for (int u = 0; u < 8; u++) {
        float rp = w[u*5+0] + ((d & 1) ? -w[u*5+4] : w[u*5+4]);
        float ip = 0.f;
        #pragma unroll
        for (int v = 1; v <= 3; v++) {
            int vd = (v * d) & 7;
            rp += 2.f * w[u*5+v] * ct[vd];
            ip += 2.f * w[u*5+v] * st[vd];
        }
        int ua = (u * a) & 7;
        re += ct[ua] * rp - st[ua] * ip;
    }
    g_gg[c*64 + t] = re * (1.f/64.f);
}

// ---------------- precompute: fused deform weight -> fp16 [k][o][c] ----------------
__global__ void k_prep_wf(const float* __restrict__ wc1, const float* __restrict__ wd) {
    int idx = blockIdx.x * blockDim.x + threadIdx.x;   // k*4096 + c*64 + o
    if (idx >= KTAPS*64*64) return;
    int o = idx & 63, c = (idx >> 6) & 63, k = idx >> 12;
    float s = 0.f;
    for (int m = 0; m < 64; m++)
        s += wc1[o*64 + m] * wd[(m*64 + c)*49 + k];
    g_wfh[k*4096 + o*64 + c] = __float2half(s);
}

// ---------------- precompute: conv3 fp16 hi/lo + proj fp16 + wpit pairs ----------------
__global__ void k_prep_tr(const float* __restrict__ wc2, const float* __restrict__ wpo,
                          const float* __restrict__ wpi) {
    int idx = blockIdx.x * blockDim.x + threadIdx.x;
    if (idx < 9*4096) {                          // [k][o][c] <- wc2[o][c][k]
        int o = idx & 63, c = (idx >> 6) & 63, k = idx >> 12;
        float s = wc2[(o*64 + c)*9 + k];
        __half hi = __float2half(s);
        float hv = __half2float(hi);
        g_wc3h[k*4096 + o*64 + c] = hi;
        g_wc3l[k*4096 + o*64 + c] = __float2half(s - hv);
    }
    if (idx < 128*128) {                         // [o][j] fp16 copy
        g_wpf[idx] = __float2half(wpo[idx]);
    }
    if (idx < 4096) {                            // [j][c] pairs
        int j = idx >> 6, c = idx & 63;
        g_wpit2[idx] = packpair(wpi[c*64 + j]);
    }
}

// ---------------- NCHW -> NHWC fp16 transpose of enc ----------------
__global__ void __launch_bounds__(256) k_transpose(const float* __restrict__ enc) {
    __shared__ float S[64][65];
    int tid = threadIdx.x;
    int p0 = blockIdx.x * 64;
    #pragma unroll
    for (int i = 0; i < 16; i++) {
        int e = i*256 + tid;
        S[e >> 6][e & 63] = enc[(e >> 6)*HWSZ + p0 + (e & 63)];
    }
    __syncthreads();
    #pragma unroll
    for (int i = 0; i < 8; i++) {
        int e2 = i*512 + tid*2;
        int lp = e2 >> 6, c = e2 & 63;
        __half2 hp = __floats2half2_rn(S[c][lp], S[c+1][lp]);
        *(__half2*)&g_encTh[p0*64 + e2] = hp;
    }
}

// ---------------- deform conv via WMMA fp16, 16x8 tile, 2-sync single-buffer pipeline ----------------
#define DF_VF   0
#define DF_WH   18432
#define DF_SIDX 27648
#define DF_SWT  29696
#define DF_SMEM 36864

__global__ void __launch_bounds__(256, 2) k_deform_wmma(const float* __restrict__ off,
                                                        const float* __restrict__ msk) {
    extern __shared__ char dsm[];
    __half* Vf = (__half*)(dsm + DF_VF);
    __half* Wh = (__half*)(dsm + DF_WH);
    int*   sIdx = (int*)(dsm + DF_SIDX);
    float* sWt  = (float*)(dsm + DF_SWT);
    const __half* encT = g_encTh;

    int tid = threadIdx.x;
    int wid = tid >> 5;
    int mg = wid & 3, ng = wid >> 2;
    int ph = blockIdx.y * 8, pw = blockIdx.x * 16;
    int ly = (tid & 127) >> 4, lx = tid & 15;
    int h = ph + ly, w = pw + lx;
    int sp = h * WW + w;

    wmma::fragment<wmma::accumulator, 16, 16, 16, float> dfr[2][2];
    #pragma unroll
    for (int mf = 0; mf < 2; mf++)
        #pragma unroll
        for (int nf = 0; nf < 2; nf++) wmma::fill_fragment(dfr[mf][nf], 0.f);

    #define STAGE_P(kk) do { \
        if (tid < 128) { \
            float dy = off[(2*(kk))*HWSZ + sp]; \
            float dx = off[(2*(kk)+1)*HWSZ + sp]; \
            float m  = msk[(kk)*HWSZ + sp]; \
            float yy = (float)(h - PADK + (kk)/7) + dy; \
            float xx = (float)(w - PADK + (kk)%7) + dx; \
            float y0f = floorf(yy), x0f = floorf(xx); \
            float wy = yy - y0f, wx = xx - x0f; \
            int y0 = (int)y0f, x0 = (int)x0f; \
            int y1 = y0 + 1,   x1 = x0 + 1; \
            bool vy0 = (y0 >= 0) && (y0 < HH), vy1 = (y1 >= 0) && (y1 < HH); \
            bool vx0 = (x0 >= 0) && (x0 < WW), vx1 = (x1 >= 0) && (x1 < WW); \
            int y0c = min(max(y0, 0), HH-1), y1c = min(max(y1, 0), HH-1); \
            int x0c = min(max(x0, 0), WW-1), x1c = min(max(x1, 0), WW-1); \
            sIdx[0*128 + tid] = (y0c*WW + x0c) * 64; \
            sIdx[1*128 + tid] = (y0c*WW + x1c) * 64; \
            sIdx[2*128 + tid] = (y1c*WW + x0c) * 64; \
            sIdx[3*128 + tid] = (y1c*WW + x1c) * 64; \
            sWt[0*128 + tid] = (vy0 && vx0) ? (1.f-wy)*(1.f-wx)*m : 0.f; \
            sWt[1*128 + tid] = (vy0 && vx1) ? (1.f-wy)*wx*m       : 0.f; \
            sWt[2*128 + tid] = (vy1 && vx0) ? wy*(1.f-wx)*m       : 0.f; \
            sWt[3*128 + tid] = (vy1 && vx1) ? wy*wx*m             : 0.f; \
        } \
    } while (0)

    #define STAGE_W(kk) do { \
        _Pragma("unroll") \
        for (int i = 0; i < 2; i++) { \
            int f = i*256 + tid; \
            int row = f >> 3, ch = f & 7; \
            *(float4*)((char*)Wh + row*144 + ch*16) = \
                *(const float4*)(g_wfh + (kk)*4096 + row*64 + ch*8); \
        } \
    } while (0)

    #define GATHER() do { \
        int c8 = tid & 7; \
        _Pragma("unroll") \
        for (int it = 0; it < 4; it++) { \
            int p = (tid >> 3) + it * 32; \
            uint4 q0 = *(const uint4*)(encT + sIdx[0*128 + p] + (c8 << 3)); \
            uint4 q1 = *(const uint4*)(encT + sIdx[1*128 + p] + (c8 << 3)); \
            uint4 q2 = *(const uint4*)(encT + sIdx[2*128 + p] + (c8 << 3)); \
            uint4 q3 = *(const uint4*)(encT + sIdx[3*128 + p] + (c8 << 3)); \
            float w0 = sWt[0*128 + p], w1 = sWt[1*128 + p]; \
            float w2 = sWt[2*128 + p], w3 = sWt[3*128 + p]; \
            const uint32_t* u0 = (const uint32_t*)&q0; \
            const uint32_t* u1 = (const uint32_t*)&q1; \
            const uint32_t* u2 = (const uint32_t*)&q2; \
            const uint32_t* u3 = (const uint32_t*)&q3; \
            uint32_t r[4]; \
            _Pragma("unroll") \
            for (int j = 0; j < 4; j++) { \
                float2 a0 = __half22float2(*(const __half2*)&u0[j]); \
                float2 a1 = __half22float2(*(const __half2*)&u1[j]); \
                float2 a2 = __half22float2(*(const __half2*)&u2[j]); \
                float2 a3 = __half22float2(*(const __half2*)&u3[j]); \
                float vx = w0*a0.x + w1*a1.x + w2*a2.x + w3*a3.x; \
                float vy = w0*a0.y + w1*a1.y + w2*a2.y + w3*a3.y; \
                asm("cvt.rn.f16x2.f32 %0, %1, %2;" : "=r"(r[j]) : "f"(vy), "f"(vx)); \
            } \
            *(uint4*)((char*)Vf + p*144 + (c8 << 4)) = *(uint4*)r; \
        } \
    } while (0)

    // prologue
    STAGE_P(0);
    __syncthreads();
    GATHER();
    STAGE_W(0);
    __syncthreads();

    for (int k = 0; k < KTAPS; k++) {
        if (k + 1 < KTAPS) STAGE_P(k + 1);
        #pragma unroll
        for (int kc = 0; kc < 4; kc++) {
            wmma::fragment<wmma::matrix_a, 16, 16, 16, __half, wmma::row_major> af[2];
            #pragma unroll
            for (int mf = 0; mf < 2; mf++)
                wmma::load_matrix_sync(af[mf], Vf + (mg*32 + mf*16)*72 + kc*16, 72);
            #pragma unroll
            for (int nf = 0; nf < 2; nf++) {
                wmma::fragment<wmma::matrix_b, 16, 16, 16, __half, wmma::col_major> bh;
                wmma::load_matrix_sync(bh, Wh + (ng*32 + nf*16)*72 + kc*16, 72);
                #pragma unroll
                for (int mf = 0; mf < 2; mf++)
                    wmma::mma_sync(dfr[mf][nf], af[mf], bh, dfr[mf][nf]);
            }
        }
        __syncthreads();
        if (k + 1 < KTAPS) {
            GATHER();
            STAGE_W(k + 1);
        }
        __syncthreads();
    }
    #undef STAGE_P
    #undef STAGE_W
    #undef GATHER

    float* Dsh = (float*)dsm;
    #pragma unroll
    for (int mf = 0; mf < 2; mf++)
        #pragma unroll
        for (int nf = 0; nf < 2; nf++)
            wmma::store_matrix_sync(Dsh + (mg*32 + mf*16)*68 + ng*32 + nf*16,
                                    dfr[mf][nf], 68, wmma::mem_row_major);
    __syncthreads();
    {
        int p = tid & 127;
        int hf = tid >> 7;
        int base = (ph + (p >> 4))*WW + pw + (p & 15);
        #pragma unroll
        for (int i = 0; i < 32; i++) {
            int o = hf*32 + i;
            g_rev[o*HWSZ + base] = Dsh[p*68 + o];
        }
    }
}

// ---------------- 1x1 conv on enc -> patch-major e2pm, 128 thr, 256 px ----------------
__global__ void __launch_bounds__(128) k_conv1x1pm(const float* __restrict__ enc) {
    __shared__ ull Wt[64*64];
    int tid = threadIdx.x;
    {
        const ulonglong2* src = (const ulonglong2*)g_wpit2;
        ulonglong2* dst = (ulonglong2*)Wt;
        #pragma unroll
        for (int i = 0; i < 16; i++) dst[tid + i*128] = src[tid + i*128];
    }
    __syncthreads();

    int base = blockIdx.x * 256;
    int p = base + (tid & 7) + (tid >> 3) * 16;
    int p2 = p + 8;

    ull acc[64];
    #pragma unroll
    for (int c = 0; c < 64; c++) acc[c] = 0ull;

    for (int j = 0; j < 64; j++) {
        ull v = pack2(enc[j*HWSZ + p], enc[j*HWSZ + p2]);
        const ulonglong2* wrow = (const ulonglong2*)(Wt + j*64);
        #pragma unroll
        for (int cc = 0; cc < 32; cc++) {
            ulonglong2 wv = wrow[cc];
            FMA2(acc[2*cc],   wv.x, v, acc[2*cc]);
            FMA2(acc[2*cc+1], wv.y, v, acc[2*cc+1]);
        }
    }

    int h = p / 192, w = p % 192;
    int q = (h & 7)*8 + (w & 7);
    int pat = (h >> 3)*24 + (w >> 3);
    #pragma unroll
    for (int c = 0; c < 64; c++)
        *(ull*)&g_e2pm[c*(64*576) + q*576 + pat] = acc[c];
}

// ---------------- per-patch circular conv as dense GEMM per channel ----------------
#define FFT_SMEM (50176 + 32768)

__global__ void __launch_bounds__(256, 2) k_fftgemm() {
    extern __shared__ char dsm[];
    float* Es = (float*)dsm;
    ull*   Wp = (ull*)(dsm + 50176);

    int tid = threadIdx.x;
    int lane = tid & 31;
    int c = blockIdx.x, pg = blockIdx.y;

    #pragma unroll
    for (int i = 0; i < 12; i++) {
        int f = i*256 + tid;
        int q = f / 48, r = f % 48;
        *(float4*)&Es[q*196 + r*4] =
            *(const float4*)&g_e2pm[c*(64*576) + q*576 + pg*192 + r*4];
    }
    #pragma unroll
    for (int i = 0; i < 16; i++) {
        int f = i*256 + tid;
        int q = f >> 6, p = f & 63;
        int idx = (((p >> 3) - (q >> 3)) & 7)*8 + (((p & 7) - (q & 7)) & 7);
        Wp[f] = packpair(g_gg[c*64 + idx]);
    }
    __syncthreads();

    int pbase = (tid >> 5) * 8;
    ull acc[8][3];
    #pragma unroll
    for (int o = 0; o < 8; o++)
        #pragma unroll
        for (int g = 0; g < 3; g++) acc[o][g] = 0ull;

    #pragma unroll 8
    for (int q = 0; q < 64; q++) {
        ull A0 = *(const ull*)&Es[q*196 + 0*64 + 2*lane];
        ull A1 = *(const ull*)&Es[q*196 + 1*64 + 2*lane];
        ull A2 = *(const ull*)&Es[q*196 + 2*64 + 2*lane];
        const ulonglong2* wp = (const ulonglong2*)(Wp + q*64 + pbase);
        ulonglong2 w01 = wp[0], w23 = wp[1], w45 = wp[2], w67 = wp[3];
        ull wv[8] = {w01.x, w01.y, w23.x, w23.y, w45.x, w45.y, w67.x, w67.y};
        #pragma unroll
        for (int o = 0; o < 8; o++) {
            FMA2(acc[o][0], wv[o], A0, acc[o][0]);
            FMA2(acc[o][1], wv[o], A1, acc[o][1]);
            FMA2(acc[o][2], wv[o], A2, acc[o][2]);
        }
    }

    float* dst = g_fft + c*HWSZ;
    #pragma unroll
    for (int o = 0; o < 8; o++) {
        int p = pbase + o;
        int py = p >> 3, px = p & 7;
        #pragma unroll
        for (int g = 0; g < 3; g++) {
            int pat = pg*192 + g*64 + 2*lane;
            float lo = __uint_as_float((unsigned int)(acc[o][g] & 0xffffffffull));
            float hi = __uint_as_float((unsigned int)(acc[o][g] >> 32));
            dst[((pat/24)*8 + py)*WW + (pat%24)*8 + px] = lo;
            pat++;
            dst[((pat/24)*8 + py)*WW + (pat%24)*8 + px] = hi;
        }
    }
}

// ---------------- fused tail: halo + conv3x3 (WMMA, W hi/lo) + proj + gate ----------------
#define T_HS   0
#define T_WC3  23040
#define T_VF   41472
#define T_E3   76288
#define T_SMEM 111104

__global__ void __launch_bounds__(256, 2) k_tail(const float* __restrict__ dec,
                                                 float* __restrict__ out) {
    extern __shared__ char dsm[];
    __half* HS  = (__half*)(dsm + T_HS);
    __half* Wa  = (__half*)(dsm + T_WC3);
    __half* Wb  = (__half*)(dsm + T_WC3 + 9216);
    __half* Vf  = (__half*)(dsm + T_VF);
    float*  Dsh = (float*)(dsm + T_VF);
    __half* E3f = (__half*)(dsm + T_E3);
    __half* Wp  = (__half*)(dsm + T_HS);

    int tid = threadIdx.x;
    int wid = tid >> 5;
    int mg = wid & 3, ng = wid >> 2;
    int ph = blockIdx.y * 8, pw = blockIdx.x * 16;

    for (int i = tid; i < 64*180; i += 256) {
        int c = i / 180, t = i - c*180;
        int hy = ph - 1 + t / 18, wx = pw - 1 + (t % 18);
        bool ok = (hy >= 0) && (hy < HH) && (wx >= 0) && (wx < WW);
        int sp = hy*WW + wx;
        float v = ok ? (g_fft[c*HWSZ + sp] + g_rev[c*HWSZ + sp]) : 0.f;
        HS[i] = __float2half(v);
    }

    wmma::fragment<wmma::accumulator, 16, 16, 16, float> a3[2][2];
    #pragma unroll
    for (int mf = 0; mf < 2; mf++)
        #pragma unroll
        for (int nf = 0; nf < 2; nf++) wmma::fill_fragment(a3[mf][nf], 0.f);

    for (int k = 0; k < 9; k++) {
        int dy = k/3 - 1, dx = k%3 - 1;
        #pragma unroll
        for (int i = 0; i < 2; i++) {
            int f = i*256 + tid;
            int row = f >> 3, ch = f & 7;
            *(float4*)((char*)Wa + row*144 + ch*16) =
                *(const float4*)(g_wc3h + k*4096 + row*64 + ch*8);
            *(float4*)((char*)Wb + row*144 + ch*16) =
                *(const float4*)(g_wc3l + k*4096 + row*64 + ch*8);
        }
        __syncthreads();
        #pragma unroll
        for (int i = 0; i < 32; i++) {
            int e = i*256 + tid;
            int c = e >> 7, p = e & 127;
            Vf[p*72 + c] = HS[c*180 + ((p >> 4) + 1 + dy)*18 + (p & 15) + 1 + dx];
        }
        __syncthreads();

        #pragma unroll
        for (int kc = 0; kc < 4; kc++) {
            wmma::fragment<wmma::matrix_a, 16, 16, 16, __half, wmma::row_major> af[2];
            #pragma unroll
            for (int mf = 0; mf < 2; mf++)
                wmma::load_matrix_sync(af[mf], Vf + (mg*32 + mf*16)*72 + kc*16, 72);
            #pragma unroll
            for (int nf = 0; nf < 2; nf++) {
                wmma::fragment<wmma::matrix_b, 16, 16, 16, __half, wmma::col_major> bh, bl;
                wmma::load_matrix_sync(bh, Wa + (ng*32 + nf*16)*72 + kc*16, 72);
                wmma::load_matrix_sync(bl, Wb + (ng*32 + nf*16)*72 + kc*16, 72);
                #pragma unroll
                for (int mf = 0; mf < 2; mf++) {
                    wmma::mma_sync(a3[mf][nf], af[mf], bh, a3[mf][nf]);
                    wmma::mma_sync(a3[mf][nf], af[mf], bl, a3[mf][nf]);
                }
            }
        }
        __syncthreads();
    }

    #pragma unroll
    for (int mf = 0; mf < 2; mf++)
        #pragma unroll
        for (int nf = 0; nf < 2; nf++)
            wmma::store_matrix_sync(Dsh + (mg*32 + mf*16)*68 + ng*32 + nf*16,
                                    a3[mf][nf], 68, wmma::mem_row_major);
    __syncthreads();

    {
        int p = tid & 127, hf = tid >> 7;
        int sp = (ph + (p >> 4))*WW + pw + (p & 15);
        #pragma unroll
        for (int i = 0; i < 32; i++) {
            int c = hf*32 + i;
            E3f[p*136 + c]      = __float2half(Dsh[p*68 + c]);
            E3f[p*136 + 64 + c] = __float2half(dec[c*HWSZ + sp]);
        }
    }
    __syncthreads();
    #pragma unroll
    for (int i = 0; i < 8; i++) {
        int f = i*256 + tid;
        int row = f >> 4, ch = f & 15;
        *(float4*)((char*)Wp + row*272 + ch*16) =
            *(const float4*)(g_wpf + row*128 + ch*8);
    }
    __syncthreads();

    wmma::fragment<wmma::accumulator, 16, 16, 16, float> a1[2][2], a2[2][2];
    #pragma unroll
    for (int mf = 0; mf < 2; mf++)
        #pragma unroll
        for (int nf = 0; nf < 2; nf++) {
            wmma::fill_fragment(a1[mf][nf], 0.f);
            wmma::fill_fragment(a2[mf][nf], 0.f);
        }

    #pragma unroll
    for (int kc = 0; kc < 8; kc++) {
        wmma::fragment<wmma::matrix_a, 16, 16, 16, __half, wmma::row_major> af[2];
        #pragma unroll
        for (int mf = 0; mf < 2; mf++)
            wmma::load_matrix_sync(af[mf], E3f + (mg*32 + mf*16)*136 + kc*16, 136);
        #pragma unroll
        for (int nf = 0; nf < 2; nf++) {
            wmma::fragment<wmma::matrix_b, 16, 16, 16, __half, wmma::col_major> b1, b2;
            wmma::load_matrix_sync(b1, Wp + (ng*32 + nf*16)*136 + kc*16, 136);
            wmma::load_matrix_sync(b2, Wp + (64 + ng*32 + nf*16)*136 + kc*16, 136);
            #pragma unroll
            for (int mf = 0; mf < 2; mf++) {
                wmma::mma_sync(a1[mf][nf], af[mf], b1, a1[mf][nf]);
                wmma::mma_sync(a2[mf][nf], af[mf], b2, a2[mf][nf]);
            }
        }
    }

    #pragma unroll
    for (int mf = 0; mf < 2; mf++)
        #pragma unroll
        for (int nf = 0; nf < 2; nf++)
            #pragma unroll
            for (int i = 0; i < a1[mf][nf].num_elements; i++)
                a1[mf][nf].x[i] *= a2[mf][nf].x[i];

    __syncthreads();
    #pragma unroll
    for (int mf = 0; mf < 2; mf++)
        #pragma unroll
        for (int nf = 0; nf < 2; nf++)
            wmma::store_matrix_sync(Dsh + (mg*32 + mf*16)*68 + ng*32 + nf*16,
                                    a1[mf][nf], 68, wmma::mem_row_major);
    __syncthreads();
    {
        int p = tid & 127, hf = tid >> 7;
        int base = (ph + (p >> 4))*WW + pw + (p & 15);
        #pragma unroll
        for (int i = 0; i < 32; i++) {
            int o = hf*32 + i;
            out[o*HWSZ + base] = Dsh[p*68 + o];
        }
    }
}

extern "C" void kernel_launch(void* const* d_in, const int* in_sizes, int n_in,
                              void* d_out, int out_size) {
    const float* enc  = (const float*)d_in[0];
    const float* dec  = (const float*)d_in[1];
    const float* ioff = (const float*)d_in[2];
    const float* iw   = (const float*)d_in[3];
    const float* wpi  = (const float*)d_in[4];
    const float* fftw = (const float*)d_in[5];
    const float* wpo  = (const float*)d_in[6];
    const float* wdef = (const float*)d_in[7];
    const float* wc1  = (const float*)d_in[8];
    const float* wc2  = (const float*)d_in[9];
    float* out = (float*)d_out;

    cudaFuncSetAttribute(k_deform_wmma, cudaFuncAttributeMaxDynamicSharedMemorySize, DF_SMEM);
    cudaFuncSetAttribute(k_fftgemm,     cudaFuncAttributeMaxDynamicSharedMemorySize, FFT_SMEM);
    cudaFuncSetAttribute(k_tail,        cudaFuncAttributeMaxDynamicSharedMemorySize, T_SMEM);

    dim3 gdef(12, 24);    // 16w x 8h tiles
    dim3 gfft(64, 3);

    k_transpose  <<<576, 256>>>(enc);
    k_prep_wf    <<<(KTAPS*4096 + 255)/256, 256>>>(wc1, wdef);
    k_prep_g     <<<64, 64>>>(fftw);
    k_deform_wmma<<<gdef, 256, DF_SMEM>>>(ioff, iw);
    k_prep_tr    <<<144, 256>>>(wc2, wpo, wpi);
    k_conv1x1pm  <<<144, 128>>>(enc);
    k_fftgemm    <<<gfft, 256, FFT_SMEM>>>();
    k_tail       <<<gdef, 256, T_SMEM>>>(dec, out);
}

// round 17
// speedup vs baseline: 1.3294x; 1.0905x over previous
#include <cuda_runtime.h>
#include <cuda_fp16.h>
#include <mma.h>
#include <cstdint>

using namespace nvcuda;

#define HH 192
#define WW 192
#define HWSZ (192*192)
#define CC 64
#define KTAPS 49
#define PADK 3

#define FMA2(d,a,b,c) asm("fma.rn.f32x2 %0, %1, %2, %3;" : "=l"(d) : "l"(a), "l"(b), "l"(c))

typedef unsigned long long ull;

__device__ __forceinline__ ull packpair(float v) {
    unsigned int u = __float_as_uint(v);
    return ((ull)u << 32) | u;
}

// ---------------- scratch (no allocs allowed) ----------------
__device__ float  g_rev [CC*HWSZ];
__device__ float  g_fft [CC*HWSZ];
__device__ __half g_encTh[HWSZ*CC];       // NHWC fp16
__device__ __half g_e2pmh[CC*64*576];     // [c][q=64][patch=576] fp16
__device__ __half g_wfh[KTAPS*64*64];     // [k][o][c] fp16 deform weight
__device__ __half g_wc3h[9*64*64];        // [k][o][c] fp16 conv3 hi
__device__ __half g_wc3l[9*64*64];        // [k][o][c] fp16 conv3 lo
__device__ __half g_wpf [128*128];        // [o128][j128] fp16 proj weight
__device__ __half g_wpih[64*64];          // [c][j] fp16 conv1x1-in hi
__device__ __half g_wpil[64*64];          // [c][j] fp16 conv1x1-in lo
__device__ float  g_gg  [64*64];          // [c][a*8+d]

// ---------------- merged prep: transpose + deform W + conv3/proj/c1x1 W + fft G ----------------
// grid: [0,576) transpose | [576,1360) deform-wf | [1360,1504) tr | [1504,1520) g
__global__ void __launch_bounds__(256) k_prep(const float* __restrict__ enc,
                                              const float* __restrict__ wc1,
                                              const float* __restrict__ wd,
                                              const float* __restrict__ wc2,
                                              const float* __restrict__ wpo,
                                              const float* __restrict__ wpi,
                                              const float* __restrict__ fw) {
    int b = blockIdx.x;
    int tid = threadIdx.x;
    if (b < 576) {
        // NCHW -> NHWC fp16 transpose of enc
        __shared__ float S[64][65];
        int p0 = b * 64;
        #pragma unroll
        for (int i = 0; i < 16; i++) {
            int e = i*256 + tid;
            S[e >> 6][e & 63] = enc[(e >> 6)*HWSZ + p0 + (e & 63)];
        }
        __syncthreads();
        #pragma unroll
        for (int i = 0; i < 8; i++) {
            int e2 = i*512 + tid*2;
            int lp = e2 >> 6, c = e2 & 63;
            __half2 hp = __floats2half2_rn(S[c][lp], S[c+1][lp]);
            *(__half2*)&g_encTh[p0*64 + e2] = hp;
        }
    } else if (b < 1360) {
        // fused deform weight -> fp16 [k][o][c]
        int idx = (b - 576) * 256 + tid;
        if (idx < KTAPS*64*64) {
            int o = idx & 63, c = (idx >> 6) & 63, k = idx >> 12;
            float s = 0.f;
            for (int m = 0; m < 64; m++)
                s += wc1[o*64 + m] * wd[(m*64 + c)*49 + k];
            g_wfh[k*4096 + o*64 + c] = __float2half(s);
        }
    } else if (b < 1504) {
        int idx = (b - 1360) * 256 + tid;
        if (idx < 9*4096) {                      // conv3 [k][o][c] hi/lo
            int o = idx & 63, c = (idx >> 6) & 63, k = idx >> 12;
            float s = wc2[(o*64 + c)*9 + k];
            __half hi = __float2half(s);
            g_wc3h[k*4096 + o*64 + c] = hi;
            g_wc3l[k*4096 + o*64 + c] = __float2half(s - __half2float(hi));
        }
        if (idx < 128*128) {                     // proj fp16 [o][j]
            g_wpf[idx] = __float2half(wpo[idx]);
        }
        if (idx < 4096) {                        // conv1x1-in [c][j] hi/lo
            float s = wpi[idx];
            __half hi = __float2half(s);
            g_wpih[idx] = hi;
            g_wpil[idx] = __float2half(s - __half2float(hi));
        }
    } else {
        // FFT filter -> circular conv kernel g_gg
        int idx = (b - 1504) * 256 + tid;        // 0..4095
        int c = idx >> 6, t = idx & 63;
        int a = t >> 3, d = t & 7;
        const float ct[8] = {1.f, 0.70710678118654752f, 0.f, -0.70710678118654752f,
                            -1.f, -0.70710678118654752f, 0.f, 0.70710678118654752f};
        const float st[8] = {0.f, 0.70710678118654752f, 1.f, 0.70710678118654752f,
                             0.f, -0.70710678118654752f, -1.f, -0.70710678118654752f};
        const float* w = fw + c * 40;
        float re = 0.f;
        for (int u = 0; u < 8; u++) {
            float rp = w[u*5+0] + ((d & 1) ? -w[u*5+4] : w[u*5+4]);
            float ip = 0.f;
            #pragma unroll
            for (int v = 1; v <= 3; v++) {
                int vd = (v * d) & 7;
                rp += 2.f * w[u*5+v] * ct[vd];
                ip += 2.f * w[u*5+v] * st[vd];
            }
            int ua = (u * a) & 7;
            re += ct[ua] * rp - st[ua] * ip;
        }
        g_gg[c*64 + t] = re * (1.f/64.f);
    }
}

// ---------------- conv1x1-in via WMMA: e2 = Wpi . enc -> fp16 patch-major ----------------
// smem: Af [128][72] fp16 18432 | Whi [64][72] 9216 | Wlo 9216 ; Dsh overlays Af
#define C1_AF 0
#define C1_WH 18432
#define C1_WL 27648
#define C1_SMEM 36864

__global__ void __launch_bounds__(256, 2) k_c1x1w() {
    extern __shared__ char dsm[];
    __half* Af = (__half*)(dsm + C1_AF);
    __half* Whi = (__half*)(dsm + C1_WH);
    __half* Wlo = (__half*)(dsm + C1_WL);
    float*  Dsh = (float*)(dsm + C1_AF);

    int tid = threadIdx.x;
    int wid = tid >> 5;
    int mg = wid & 3, ng = wid >> 2;
    int ph = blockIdx.y * 8, pw = blockIdx.x * 16;

    // stage A: 128 px rows x 64 j halves (coalesced uint4)
    #pragma unroll
    for (int i = 0; i < 4; i++) {
        int f = i*256 + tid;             // 0..1023 : row = f>>3, ch8 = (f&7)*8
        int row = f >> 3, ch8 = (f & 7) * 8;
        int sp = (ph + (row >> 4))*WW + pw + (row & 15);
        *(uint4*)((char*)Af + row*144 + ch8*2) =
            *(const uint4*)(g_encTh + sp*64 + ch8);
    }
    // stage W hi/lo
    #pragma unroll
    for (int i = 0; i < 2; i++) {
        int f = i*256 + tid;
        int row = f >> 3, ch = f & 7;
        *(float4*)((char*)Whi + row*144 + ch*16) = *(const float4*)(g_wpih + row*64 + ch*8);
        *(float4*)((char*)Wlo + row*144 + ch*16) = *(const float4*)(g_wpil + row*64 + ch*8);
    }
    __syncthreads();

    wmma::fragment<wmma::accumulator, 16, 16, 16, float> ac[2][2];
    #pragma unroll
    for (int mf = 0; mf < 2; mf++)
        #pragma unroll
        for (int nf = 0; nf < 2; nf++) wmma::fill_fragment(ac[mf][nf], 0.f);

    #pragma unroll
    for (int kc = 0; kc < 4; kc++) {
        wmma::fragment<wmma::matrix_a, 16, 16, 16, __half, wmma::row_major> af[2];
        #pragma unroll
        for (int mf = 0; mf < 2; mf++)
            wmma::load_matrix_sync(af[mf], Af + (mg*32 + mf*16)*72 + kc*16, 72);
        #pragma unroll
        for (int nf = 0; nf < 2; nf++) {
            wmma::fragment<wmma::matrix_b, 16, 16, 16, __half, wmma::col_major> bh, bl;
            wmma::load_matrix_sync(bh, Whi + (ng*32 + nf*16)*72 + kc*16, 72);
            wmma::load_matrix_sync(bl, Wlo + (ng*32 + nf*16)*72 + kc*16, 72);
            #pragma unroll
            for (int mf = 0; mf < 2; mf++) {
                wmma::mma_sync(ac[mf][nf], af[mf], bh, ac[mf][nf]);
                wmma::mma_sync(ac[mf][nf], af[mf], bl, ac[mf][nf]);
            }
        }
    }
    __syncthreads();

    #pragma unroll
    for (int mf = 0; mf < 2; mf++)
        #pragma unroll
        for (int nf = 0; nf < 2; nf++)
            wmma::store_matrix_sync(Dsh + (mg*32 + mf*16)*68 + ng*32 + nf*16,
                                    ac[mf][nf], 68, wmma::mem_row_major);
    __syncthreads();

    // writeout: fp16 patch-major, same-q pixel pairs (px, px+8) -> half2 STG.32
    {
        int pg4 = tid >> 6;              // channel group 0..3 (16 ch each)
        int pr  = tid & 63;              // pair index: py = pr>>3, pxl = pr&7
        int py = pr >> 3, pxl = pr & 7;
        int p0 = py*16 + pxl, p1 = p0 + 8;
        int q  = py*8 + pxl;
        int pat = ((ph + py) >> 3)*24 + ((pw + pxl) >> 3);   // even; pat+1 is the pair
        #pragma unroll
        for (int i = 0; i < 16; i++) {
            int c = pg4*16 + i;
            __half2 hv = __floats2half2_rn(Dsh[p0*68 + c], Dsh[p1*68 + c]);
            *(__half2*)&g_e2pmh[c*(64*576) + q*576 + pat] = hv;
        }
    }
}

// ---------------- deform conv via WMMA fp16, 16x8 tile, 2-sync pipeline ----------------
#define DF_VF   0
#define DF_WH   18432
#define DF_SIDX 27648
#define DF_SWT  29696
#define DF_SMEM 36864

__global__ void __launch_bounds__(256, 2) k_deform_wmma(const float* __restrict__ off,
                                                        const float* __restrict__ msk) {
    extern __shared__ char dsm[];
    __half* Vf = (__half*)(dsm + DF_VF);
    __half* Wh = (__half*)(dsm + DF_WH);
    int*   sIdx = (int*)(dsm + DF_SIDX);
    float* sWt  = (float*)(dsm + DF_SWT);
    const __half* encT = g_encTh;

    int tid = threadIdx.x;
    int wid = tid >> 5;
    int mg = wid & 3, ng = wid >> 2;
    int ph = blockIdx.y * 8, pw = blockIdx.x * 16;
    int ly = (tid & 127) >> 4, lx = tid & 15;
    int h = ph + ly, w = pw + lx;
    int sp = h * WW + w;

    wmma::fragment<wmma::accumulator, 16, 16, 16, float> dfr[2][2];
    #pragma unroll
    for (int mf = 0; mf < 2; mf++)
        #pragma unroll
        for (int nf = 0; nf < 2; nf++) wmma::fill_fragment(dfr[mf][nf], 0.f);

    #define STAGE_P(kk) do { \
        if (tid < 128) { \
            float dy = off[(2*(kk))*HWSZ + sp]; \
            float dx = off[(2*(kk)+1)*HWSZ + sp]; \
            float m  = msk[(kk)*HWSZ + sp]; \
            float yy = (float)(h - PADK + (kk)/7) + dy; \
            float xx = (float)(w - PADK + (kk)%7) + dx; \
            float y0f = floorf(yy), x0f = floorf(xx); \
            float wy = yy - y0f, wx = xx - x0f; \
            int y0 = (int)y0f, x0 = (int)x0f; \
            int y1 = y0 + 1,   x1 = x0 + 1; \
            bool vy0 = (y0 >= 0) && (y0 < HH), vy1 = (y1 >= 0) && (y1 < HH); \
            bool vx0 = (x0 >= 0) && (x0 < WW), vx1 = (x1 >= 0) && (x1 < WW); \
            int y0c = min(max(y0, 0), HH-1), y1c = min(max(y1, 0), HH-1); \
            int x0c = min(max(x0, 0), WW-1), x1c = min(max(x1, 0), WW-1); \
            sIdx[0*128 + tid] = (y0c*WW + x0c) * 64; \
            sIdx[1*128 + tid] = (y0c*WW + x1c) * 64; \
            sIdx[2*128 + tid] = (y1c*WW + x0c) * 64; \
            sIdx[3*128 + tid] = (y1c*WW + x1c) * 64; \
            sWt[0*128 + tid] = (vy0 && vx0) ? (1.f-wy)*(1.f-wx)*m : 0.f; \
            sWt[1*128 + tid] = (vy0 && vx1) ? (1.f-wy)*wx*m       : 0.f; \
            sWt[2*128 + tid] = (vy1 && vx0) ? wy*(1.f-wx)*m       : 0.f; \
            sWt[3*128 + tid] = (vy1 && vx1) ? wy*wx*m             : 0.f; \
        } \
    } while (0)

    #define STAGE_W(kk) do { \
        _Pragma("unroll") \
        for (int i = 0; i < 2; i++) { \
            int f = i*256 + tid; \
            int row = f >> 3, ch = f & 7; \
            *(float4*)((char*)Wh + row*144 + ch*16) = \
                *(const float4*)(g_wfh + (kk)*4096 + row*64 + ch*8); \
        } \
    } while (0)

    #define GATHER() do { \
        int c8 = tid & 7; \
        _Pragma("unroll") \
        for (int it = 0; it < 4; it++) { \
            int p = (tid >> 3) + it * 32; \
            uint4 q0 = *(const uint4*)(encT + sIdx[0*128 + p] + (c8 << 3)); \
            uint4 q1 = *(const uint4*)(encT + sIdx[1*128 + p] + (c8 << 3)); \
            uint4 q2 = *(const uint4*)(encT + sIdx[2*128 + p] + (c8 << 3)); \
            uint4 q3 = *(const uint4*)(encT + sIdx[3*128 + p] + (c8 << 3)); \
            float w0 = sWt[0*128 + p], w1 = sWt[1*128 + p]; \
            float w2 = sWt[2*128 + p], w3 = sWt[3*128 + p]; \
            const uint32_t* u0 = (const uint32_t*)&q0; \
            const uint32_t* u1 = (const uint32_t*)&q1; \
            const uint32_t* u2 = (const uint32_t*)&q2; \
            const uint32_t* u3 = (const uint32_t*)&q3; \
            uint32_t r[4]; \
            _Pragma("unroll") \
            for (int j = 0; j < 4; j++) { \
                float2 a0 = __half22float2(*(const __half2*)&u0[j]); \
                float2 a1 = __half22float2(*(const __half2*)&u1[j]); \
                float2 a2 = __half22float2(*(const __half2*)&u2[j]); \
                float2 a3 = __half22float2(*(const __half2*)&u3[j]); \
                float vx = w0*a0.x + w1*a1.x + w2*a2.x + w3*a3.x; \
                float vy = w0*a0.y + w1*a1.y + w2*a2.y + w3*a3.y; \
                asm("cvt.rn.f16x2.f32 %0, %1, %2;" : "=r"(r[j]) : "f"(vy), "f"(vx)); \
            } \
            *(uint4*)((char*)Vf + p*144 + (c8 << 4)) = *(uint4*)r; \
        } \
    } while (0)

    STAGE_P(0);
    __syncthreads();
    GATHER();
    STAGE_W(0);
    __syncthreads();

    for (int k = 0; k < KTAPS; k++) {
        if (k + 1 < KTAPS) STAGE_P(k + 1);
        #pragma unroll
        for (int kc = 0; kc < 4; kc++) {
            wmma::fragment<wmma::matrix_a, 16, 16, 16, __half, wmma::row_major> af[2];
            #pragma unroll
            for (int mf = 0; mf < 2; mf++)
                wmma::load_matrix_sync(af[mf], Vf + (mg*32 + mf*16)*72 + kc*16, 72);
            #pragma unroll
            for (int nf = 0; nf < 2; nf++) {
                wmma::fragment<wmma::matrix_b, 16, 16, 16, __half, wmma::col_major> bh;
                wmma::load_matrix_sync(bh, Wh + (ng*32 + nf*16)*72 + kc*16, 72);
                #pragma unroll
                for (int mf = 0; mf < 2; mf++)
                    wmma::mma_sync(dfr[mf][nf], af[mf], bh, dfr[mf][nf]);
            }
        }
        __syncthreads();
        if (k + 1 < KTAPS) {
            GATHER();
            STAGE_W(k + 1);
        }
        __syncthreads();
    }
    #undef STAGE_P
    #undef STAGE_W
    #undef GATHER

    float* Dsh = (float*)dsm;
    #pragma unroll
    for (int mf = 0; mf < 2; mf++)
        #pragma unroll
        for (int nf = 0; nf < 2; nf++)
            wmma::store_matrix_sync(Dsh + (mg*32 + mf*16)*68 + ng*32 + nf*16,
                                    dfr[mf][nf], 68, wmma::mem_row_major);
    __syncthreads();
    {
        int p = tid & 127;
        int hf = tid >> 7;
        int base = (ph + (p >> 4))*WW + pw + (p & 15);
        #pragma unroll
        for (int i = 0; i < 32; i++) {
            int o = hf*32 + i;
            g_rev[o*HWSZ + base] = Dsh[p*68 + o];
        }
    }
}

// ---------------- per-patch circular conv as dense GEMM per channel (fp16 input) ----------------
#define FFT_SMEM (50176 + 32768)

__global__ void __launch_bounds__(256, 2) k_fftgemm() {
    extern __shared__ char dsm[];
    float* Es = (float*)dsm;
    ull*   Wp = (ull*)(dsm + 50176);

    int tid = threadIdx.x;
    int lane = tid & 31;
    int c = blockIdx.x, pg = blockIdx.y;

    #pragma unroll
    for (int i = 0; i < 12; i++) {
        int f = i*256 + tid;
        int q = f / 48, r = f % 48;
        uint2 hv = *(const uint2*)&g_e2pmh[c*(64*576) + q*576 + pg*192 + r*4];
        float2 lo = __half22float2(*(__half2*)&hv.x);
        float2 hi = __half22float2(*(__half2*)&hv.y);
        *(float4*)&Es[q*196 + r*4] = make_float4(lo.x, lo.y, hi.x, hi.y);
    }
    #pragma unroll
    for (int i = 0; i < 16; i++) {
        int f = i*256 + tid;
        int q = f >> 6, p = f & 63;
        int idx = (((p >> 3) - (q >> 3)) & 7)*8 + (((p & 7) - (q & 7)) & 7);
        Wp[f] = packpair(g_gg[c*64 + idx]);
    }
    __syncthreads();

    int pbase = (tid >> 5) * 8;
    ull acc[8][3];
    #pragma unroll
    for (int o = 0; o < 8; o++)
        #pragma unroll
        for (int g = 0; g < 3; g++) acc[o][g] = 0ull;

    #pragma unroll 8
    for (int q = 0; q < 64; q++) {
        ull A0 = *(const ull*)&Es[q*196 + 0*64 + 2*lane];
        ull A1 = *(const ull*)&Es[q*196 + 1*64 + 2*lane];
        ull A2 = *(const ull*)&Es[q*196 + 2*64 + 2*lane];
        const ulonglong2* wp = (const ulonglong2*)(Wp + q*64 + pbase);
        ulonglong2 w01 = wp[0], w23 = wp[1], w45 = wp[2], w67 = wp[3];
        ull wv[8] = {w01.x, w01.y, w23.x, w23.y, w45.x, w45.y, w67.x, w67.y};
        #pragma unroll
        for (int o = 0; o < 8; o++) {
            FMA2(acc[o][0], wv[o], A0, acc[o][0]);
            FMA2(acc[o][1], wv[o], A1, acc[o][1]);
            FMA2(acc[o][2], wv[o], A2, acc[o][2]);
        }
    }

    float* dst = g_fft + c*HWSZ;
    #pragma unroll
    for (int o = 0; o < 8; o++) {
        int p = pbase + o;
        int py = p >> 3, px = p & 7;
        #pragma unroll
        for (int g = 0; g < 3; g++) {
            int pat = pg*192 + g*64 + 2*lane;
            float lo = __uint_as_float((unsigned int)(acc[o][g] & 0xffffffffull));
            float hi = __uint_as_float((unsigned int)(acc[o][g] >> 32));
            dst[((pat/24)*8 + py)*WW + (pat%24)*8 + px] = lo;
            pat++;
            dst[((pat/24)*8 + py)*WW + (pat%24)*8 + px] = hi;
        }
    }
}

// ---------------- fused tail: halo + conv3x3 (WMMA, W hi/lo) + proj + gate ----------------
#define T_HS   0
#define T_WC3  23040
#define T_VF   41472
#define T_E3   76288
#define T_SMEM 111104

__global__ void __launch_bounds__(256, 2) k_tail(const float* __restrict__ dec,
                                                 float* __restrict__ out) {
    extern __shared__ char dsm[];
    __half* HS  = (__half*)(dsm + T_HS);
    __half* Wa  = (__half*)(dsm + T_WC3);
    __half* Wb  = (__half*)(dsm + T_WC3 + 9216);
    __half* Vf  = (__half*)(dsm + T_VF);
    float*  Dsh = (float*)(dsm + T_VF);
    __half* E3f = (__half*)(dsm + T_E3);
    __half* Wp  = (__half*)(dsm + T_HS);

    int tid = threadIdx.x;
    int wid = tid >> 5;
    int mg = wid & 3, ng = wid >> 2;
    int ph = blockIdx.y * 8, pw = blockIdx.x * 16;

    for (int i = tid; i < 64*180; i += 256) {
        int c = i / 180, t = i - c*180;
        int hy = ph - 1 + t / 18, wx = pw - 1 + (t % 18);
        bool ok = (hy >= 0) && (hy < HH) && (wx >= 0) && (wx < WW);
        int sp = hy*WW + wx;
        float v = ok ? (g_fft[c*HWSZ + sp] + g_rev[c*HWSZ + sp]) : 0.f;
        HS[i] = __float2half(v);
    }

    wmma::fragment<wmma::accumulator, 16, 16, 16, float> a3[2][2];
    #pragma unroll
    for (int mf = 0; mf < 2; mf++)
        #pragma unroll
        for (int nf = 0; nf < 2; nf++) wmma::fill_fragment(a3[mf][nf], 0.f);

    for (int k = 0; k < 9; k++) {
        int dy = k/3 - 1, dx = k%3 - 1;
        #pragma unroll
        for (int i = 0; i < 2; i++) {
            int f = i*256 + tid;
            int row = f >> 3, ch = f & 7;
            *(float4*)((char*)Wa + row*144 + ch*16) =
                *(const float4*)(g_wc3h + k*4096 + row*64 + ch*8);
            *(float4*)((char*)Wb + row*144 + ch*16) =
                *(const float4*)(g_wc3l + k*4096 + row*64 + ch*8);
        }
        __syncthreads();
        #pragma unroll
        for (int i = 0; i < 32; i++) {
            int e = i*256 + tid;
            int c = e >> 7, p = e & 127;
            Vf[p*72 + c] = HS[c*180 + ((p >> 4) + 1 + dy)*18 + (p & 15) + 1 + dx];
        }
        __syncthreads();

        #pragma unroll
        for (int kc = 0; kc < 4; kc++) {
            wmma::fragment<wmma::matrix_a, 16, 16, 16, __half, wmma::row_major> af[2];
            #pragma unroll
            for (int mf = 0; mf < 2; mf++)
                wmma::load_matrix_sync(af[mf], Vf + (mg*32 + mf*16)*72 + kc*16, 72);
            #pragma unroll
            for (int nf = 0; nf < 2; nf++) {
                wmma::fragment<wmma::matrix_b, 16, 16, 16, __half, wmma::col_major> bh, bl;
                wmma::load_matrix_sync(bh, Wa + (ng*32 + nf*16)*72 + kc*16, 72);
                wmma::load_matrix_sync(bl, Wb + (ng*32 + nf*16)*72 + kc*16, 72);
                #pragma unroll
                for (int mf = 0; mf < 2; mf++) {
                    wmma::mma_sync(a3[mf][nf], af[mf], bh, a3[mf][nf]);
                    wmma::mma_sync(a3[mf][nf], af[mf], bl, a3[mf][nf]);
                }
            }
        }
        __syncthreads();
    }

    #pragma unroll
    for (int mf = 0; mf < 2; mf++)
        #pragma unroll
        for (int nf = 0; nf < 2; nf++)
            wmma::store_matrix_sync(Dsh + (mg*32 + mf*16)*68 + ng*32 + nf*16,
                                    a3[mf][nf], 68, wmma::mem_row_major);
    __syncthreads();

    {
        int p = tid & 127, hf = tid >> 7;
        int sp = (ph + (p >> 4))*WW + pw + (p & 15);
        #pragma unroll
        for (int i = 0; i < 32; i++) {
            int c = hf*32 + i;
            E3f[p*136 + c]      = __float2half(Dsh[p*68 + c]);
            E3f[p*136 + 64 + c] = __float2half(dec[c*HWSZ + sp]);
        }
    }
    __syncthreads();
    #pragma unroll
    for (int i = 0; i < 8; i++) {
        int f = i*256 + tid;
        int row = f >> 4, ch = f & 15;
        *(float4*)((char*)Wp + row*272 + ch*16) =
            *(const float4*)(g_wpf + row*128 + ch*8);
    }
    __syncthreads();

    wmma::fragment<wmma::accumulator, 16, 16, 16, float> a1[2][2], a2[2][2];
    #pragma unroll
    for (int mf = 0; mf < 2; mf++)
        #pragma unroll
        for (int nf = 0; nf < 2; nf++) {
            wmma::fill_fragment(a1[mf][nf], 0.f);
            wmma::fill_fragment(a2[mf][nf], 0.f);
        }

    #pragma unroll
    for (int kc = 0; kc < 8; kc++) {
        wmma::fragment<wmma::matrix_a, 16, 16, 16, __half, wmma::row_major> af[2];
        #pragma unroll
        for (int mf = 0; mf < 2; mf++)
            wmma::load_matrix_sync(af[mf], E3f + (mg*32 + mf*16)*136 + kc*16, 136);
        #pragma unroll
        for (int nf = 0; nf < 2; nf++) {
            wmma::fragment<wmma::matrix_b, 16, 16, 16, __half, wmma::col_major> b1, b2;
            wmma::load_matrix_sync(b1, Wp + (ng*32 + nf*16)*136 + kc*16, 136);
            wmma::load_matrix_sync(b2, Wp + (64 + ng*32 + nf*16)*136 + kc*16, 136);
            #pragma unroll
            for (int mf = 0; mf < 2; mf++) {
                wmma::mma_sync(a1[mf][nf], af[mf], b1, a1[mf][nf]);
                wmma::mma_sync(a2[mf][nf], af[mf], b2, a2[mf][nf]);
            }
        }
    }

    #pragma unroll
    for (int mf = 0; mf < 2; mf++)
        #pragma unroll
        for (int nf = 0; nf < 2; nf++)
            #pragma unroll
            for (int i = 0; i < a1[mf][nf].num_elements; i++)
                a1[mf][nf].x[i] *= a2[mf][nf].x[i];

    __syncthreads();
    #pragma unroll
    for (int mf = 0; mf < 2; mf++)
        #pragma unroll
        for (int nf = 0; nf < 2; nf++)
            wmma::store_matrix_sync(Dsh + (mg*32 + mf*16)*68 + ng*32 + nf*16,
                                    a1[mf][nf], 68, wmma::mem_row_major);
    __syncthreads();
    {
        int p = tid & 127, hf = tid >> 7;
        int base = (ph + (p >> 4))*WW + pw + (p & 15);
        #pragma unroll
        for (int i = 0; i < 32; i++) {
            int o = hf*32 + i;
            out[o*HWSZ + base] = Dsh[p*68 + o];
        }
    }
}

extern "C" void kernel_launch(void* const* d_in, const int* in_sizes, int n_in,
                              void* d_out, int out_size) {
    const float* enc  = (const float*)d_in[0];
    const float* dec  = (const float*)d_in[1];
    const float* ioff = (const float*)d_in[2];
    const float* iw   = (const float*)d_in[3];
    const float* wpi  = (const float*)d_in[4];
    const float* fftw = (const float*)d_in[5];
    const float* wpo  = (const float*)d_in[6];
    const float* wdef = (const float*)d_in[7];
    const float* wc1  = (const float*)d_in[8];
    const float* wc2  = (const float*)d_in[9];
    float* out = (float*)d_out;

    cudaFuncSetAttribute(k_c1x1w,       cudaFuncAttributeMaxDynamicSharedMemorySize, C1_SMEM);
    cudaFuncSetAttribute(k_deform_wmma, cudaFuncAttributeMaxDynamicSharedMemorySize, DF_SMEM);
    cudaFuncSetAttribute(k_fftgemm,     cudaFuncAttributeMaxDynamicSharedMemorySize, FFT_SMEM);
    cudaFuncSetAttribute(k_tail,        cudaFuncAttributeMaxDynamicSharedMemorySize, T_SMEM);

    dim3 gdef(12, 24);    // 16w x 8h tiles
    dim3 gfft(64, 3);

    k_prep       <<<1520, 256>>>(enc, wc1, wdef, wc2, wpo, wpi, fftw);
    k_c1x1w      <<<gdef, 256, C1_SMEM>>>();
    k_deform_wmma<<<gdef, 256, DF_SMEM>>>(ioff, iw);
    k_fftgemm    <<<gfft, 256, FFT_SMEM>>>();
    k_tail       <<<gdef, 256, T_SMEM>>>(dec, out);
}